// round 14
// baseline (speedup 1.0000x reference)
#include <cuda_runtime.h>
#include <cuda_bf16.h>
#include <cstdint>

// LSTM: B=32, T=1024, D=1024, H=128  (gates 4H=512, order i,f,g,o)
// out layout: [B*T*H floats][h_n: B*H][c_n: B*H]

#define B_ 32
#define T_ 1024
#define D_ 1024
#define H_ 128
#define G_ 512
#define GEMM_CTAS 116     // 1 CTA/SM; rec takes the other 32 SMs (148 total)
#define STAGE_BYTES 32768 // A 16KB + B 16KB per stage, 3 stages (128x128 tile)
#define GEMM_SMEM_PAD 122880  // 120KB: forces 1 GEMM CTA/SM, blocks rec colocation
#define REC_SMEM_PAD  116736  // 114KB: forces 1 rec CTA/SM, blocks GEMM colocation

typedef unsigned long long u64;

__device__ __forceinline__ u64 pk2(float x, float y) {
    u64 r;
    asm("mov.b64 %0, {%1, %2};" : "=l"(r)
        : "r"(__float_as_uint(x)), "r"(__float_as_uint(y)));
    return r;
}
__device__ __forceinline__ float2 upk2(u64 v) {
    unsigned lo, hi;
    asm("mov.b64 {%0, %1}, %2;" : "=r"(lo), "=r"(hi) : "l"(v));
    return make_float2(__uint_as_float(lo), __uint_as_float(hi));
}
__device__ __forceinline__ void fma2(u64 &c, u64 a, u64 b) {
    asm("fma.rn.f32x2 %0, %1, %2, %0;" : "+l"(c) : "l"(a), "l"(b));
}
__device__ __forceinline__ float fast_sigmoid(float x) {
    return 1.0f / (1.0f + __expf(-x));
}
__device__ __forceinline__ float fast_tanh(float x) {
    return 1.0f - 2.0f / (__expf(2.0f * x) + 1.0f);
}
__device__ __forceinline__ uint32_t smem_u32(const void* p) {
    uint32_t a;
    asm("{ .reg .u64 t; cvta.to.shared.u64 t, %1; cvt.u32.u64 %0, t; }"
        : "=r"(a) : "l"(p));
    return a;
}
// L2-coherent load for data written concurrently by another kernel.
// (NOT __ldg/ld.global.nc: the nc path may serve stale lines past the
//  flag acquire when the consumer runs at the producer's frontier.)
__device__ __forceinline__ float ldcg(const float* p) {
    float v;
    asm volatile("ld.global.cg.f32 %0, [%1];" : "=f"(v) : "l"(p) : "memory");
    return v;
}
__device__ __forceinline__ void cp16(uint32_t dst, const void* src) {
    asm volatile("cp.async.cg.shared.global [%0], [%1], 16;"
                 :: "r"(dst), "l"(src));
}
__device__ __forceinline__ void ldsm4(uint32_t* r, uint32_t addr) {
    asm volatile("ldmatrix.sync.aligned.m8n8.x4.shared.b16 {%0,%1,%2,%3}, [%4];"
                 : "=r"(r[0]), "=r"(r[1]), "=r"(r[2]), "=r"(r[3]) : "r"(addr));
}
__device__ __forceinline__ void mma16816(float* d, const uint32_t* a,
                                         uint32_t b0, uint32_t b1) {
    asm volatile(
        "mma.sync.aligned.m16n8k16.row.col.f32.bf16.bf16.f32 "
        "{%0,%1,%2,%3}, {%4,%5,%6,%7}, {%8,%9}, {%0,%1,%2,%3};"
        : "+f"(d[0]), "+f"(d[1]), "+f"(d[2]), "+f"(d[3])
        : "r"(a[0]), "r"(a[1]), "r"(a[2]), "r"(a[3]), "r"(b0), "r"(b1));
}

// Scratch (__device__ globals: allocation-free)
__device__ float g_gx[(size_t)B_ * T_ * G_];                 // 64 MB
__device__ __nv_bfloat16 g_A2[(size_t)B_ * T_ * 2048];       // 128 MB  [hi|mid]
__device__ __nv_bfloat16 g_B2[(size_t)G_ * 2048];            // 2 MB    [hi|mid]
__device__ int g_flag[256];   // per m-tile completion counters (target 4)

__global__ void reset_flags() { g_flag[threadIdx.x] = 0; }

// ---------------------------------------------------------------------------
// fp32 -> 2-way bf16 split: hi = rn(x), mid = rn(x - hi); x ~= hi+mid (2^-17)
// ---------------------------------------------------------------------------
__global__ void convert_split2(const float* __restrict__ X,
                               __nv_bfloat16* __restrict__ OUT, int rows)
{
    size_t i = (size_t)blockIdx.x * blockDim.x + threadIdx.x;
    size_t total = (size_t)rows * (D_ / 4);
    if (i >= total) return;
    float4 v = ((const float4*)X)[i];
    size_t m  = i >> 8;
    int   k4  = (int)(i & 255);

    float xs[4] = {v.x, v.y, v.z, v.w};
    __nv_bfloat16 hi[4], md[4];
#pragma unroll
    for (int c = 0; c < 4; c++) {
        hi[c] = __float2bfloat16(xs[c]);
        float r1 = xs[c] - __bfloat162float(hi[c]);
        md[c] = __float2bfloat16(r1);
    }

    __nv_bfloat162* dh = (__nv_bfloat162*)(OUT + m * 2048 + k4 * 4);
    __nv_bfloat162* dm = (__nv_bfloat162*)(OUT + m * 2048 + 1024 + k4 * 4);
    dh[0] = __halves2bfloat162(hi[0], hi[1]);
    dh[1] = __halves2bfloat162(hi[2], hi[3]);
    dm[0] = __halves2bfloat162(md[0], md[1]);
    dm[1] = __halves2bfloat162(md[2], md[3]);
}

// ---------------------------------------------------------------------------
// PERSISTENT bf16 mma.sync GEMM, 3 phases (h,h)(h,m)(m,h).
// HW-capped at ~336 MAC/cyc/SM (legacy HMMA) -> span scales with SM count.
// 128x128 tiles, 116 CTAs (1/SM via 120KB smem pad), 3-stage cp.async,
// tc-major tile order; each m-tile's 4 n-CTAs bump g_flag[y].
// ---------------------------------------------------------------------------
__global__ __launch_bounds__(256, 1) void gemm_mma_x(
    const __nv_bfloat16* __restrict__ A2, const __nv_bfloat16* __restrict__ B2,
    const float* __restrict__ b1, const float* __restrict__ b2,
    float* __restrict__ GX)
{
    extern __shared__ char smraw[];
    const uint32_t sbase = smem_u32(smraw);

    const int tid = threadIdx.x;
    const int wid = tid >> 5, lid = tid & 31;
    const int wm  = wid >> 2, wn = wid & 3;     // 2 x 4 warps, 64x32 each
    const int mat = lid >> 3, rin = lid & 7;
    const uint32_t aOff = (uint32_t)((((wm * 8 + (mat & 1)) * 8) + (mat >> 1)) * 128 + rin * 16);
    const uint32_t bOff = 16384u +
        (uint32_t)((((wn * 4 + (mat & 1)) * 8) + (mat >> 1)) * 128 + rin * 16);

    for (int tile = blockIdx.x; tile < 1024; tile += gridDim.x) {
        const int y  = tile >> 2;            // m-tile index, tc-major
        const int n0 = (tile & 3) * 128;
        const int bb = y & 31, tc = y >> 5;
        const int m0 = bb * 1024 + tc * 128;

        const char* Ab = (const char*)A2 + (size_t)m0 * 4096;
        const char* Bb = (const char*)B2 + (size_t)n0 * 4096;

        float acc[4][4][4];
#pragma unroll
        for (int i = 0; i < 4; i++)
#pragma unroll
            for (int j = 0; j < 4; j++)
#pragma unroll
                for (int r = 0; r < 4; r++) acc[i][j][r] = 0.0f;

#define ISSUE(kt, st)                                                          \
    do {                                                                       \
        const int ph_ = (kt) >> 4, kk_ = (kt) & 15;                            \
        const int aoff_ = ((ph_ == 2) ? 2048 : 0) + kk_ * 128;                 \
        const int boff_ = ((ph_ == 1) ? 2048 : 0) + kk_ * 128;                 \
        uint32_t dA = sbase + (st) * STAGE_BYTES;                              \
        uint32_t dB = dA + 16384;                                              \
        _Pragma("unroll")                                                      \
        for (int it = 0; it < 4; it++) {                                       \
            int id = tid + it * 256;                                           \
            int mm = id >> 3, kg = id & 7;                                     \
            uint32_t doff = (uint32_t)((((mm >> 3) * 8) + kg) * 128 + (mm & 7) * 16); \
            cp16(dA + doff, Ab + (size_t)mm * 4096 + aoff_ + kg * 16);         \
            cp16(dB + doff, Bb + (size_t)mm * 4096 + boff_ + kg * 16);         \
        }                                                                      \
        asm volatile("cp.async.commit_group;" ::: "memory");                   \
    } while (0)

        ISSUE(0, 0);
        ISSUE(1, 1);

        const int NKT = 48;
        for (int kt = 0; kt < NKT; kt++) {
            const int st = kt % 3;
            if (kt + 1 < NKT) {
                asm volatile("cp.async.wait_group 1;" ::: "memory");
            } else {
                asm volatile("cp.async.wait_group 0;" ::: "memory");
            }
            __syncthreads();
            if (kt + 2 < NKT) ISSUE(kt + 2, (kt + 2) % 3);

            const uint32_t aS = sbase + st * STAGE_BYTES + aOff;
            const uint32_t bS = sbase + st * STAGE_BYTES + bOff;
#pragma unroll
            for (int ks = 0; ks < 4; ks++) {
                uint32_t af[4][4], bf[2][4];
#pragma unroll
                for (int i = 0; i < 4; i++)
                    ldsm4(af[i], aS + i * 2048 + ks * 256);
#pragma unroll
                for (int jp = 0; jp < 2; jp++)
                    ldsm4(bf[jp], bS + jp * 2048 + ks * 256);
#pragma unroll
                for (int i = 0; i < 4; i++)
#pragma unroll
                    for (int j = 0; j < 4; j++)
                        mma16816(acc[i][j], af[i],
                                 bf[j >> 1][j & 1], bf[j >> 1][2 + (j & 1)]);
            }
        }

        // Epilogue: bias + store fp32, then signal tile completion
        const int mrow = lid >> 2;
        const int ncol = 2 * (lid & 3);
        float2 bj[4];
#pragma unroll
        for (int j = 0; j < 4; j++) {
            int n = n0 + wn * 32 + j * 8 + ncol;
            bj[j].x = b1[n] + b2[n];
            bj[j].y = b1[n + 1] + b2[n + 1];
        }
#pragma unroll
        for (int i = 0; i < 4; i++) {
            int r0 = m0 + wm * 64 + i * 16 + mrow;
#pragma unroll
            for (int j = 0; j < 4; j++) {
                int n = n0 + wn * 32 + j * 8 + ncol;
                float2 v0 = make_float2(acc[i][j][0] + bj[j].x, acc[i][j][1] + bj[j].y);
                float2 v1 = make_float2(acc[i][j][2] + bj[j].x, acc[i][j][3] + bj[j].y);
                *(float2*)&GX[(size_t)r0 * G_ + n]        = v0;
                *(float2*)&GX[(size_t)(r0 + 8) * G_ + n]  = v1;
            }
        }
        __threadfence();
        __syncthreads();
        if (tid == 0) atomicAdd(&g_flag[y], 1);
    }
}

// ---------------------------------------------------------------------------
// Recurrence v5: ONE CTA per batch (32 CTAs, 512 threads). Thread t = gate
// row t. W_hh row split: 80 floats in registers + 48 floats in smem
// ([12 chunks][512 rows][4] -> conflict-free LDS.128). No cluster/DSMEM/shfl.
// gx read with ld.global.cg (L2-coherent; gx is produced concurrently).
// Tile gating on g_flag (target 4) + boundary-safe gx prefetch.
// ---------------------------------------------------------------------------
#define RC 20   // register chunks (80 floats); smem chunks = 12 (48 floats)

__global__ __launch_bounds__(512, 1) void lstm_rec5(
    const float* __restrict__ GX, const float* __restrict__ Wh,
    float* __restrict__ out, float* __restrict__ hn, float* __restrict__ cn)
{
    extern __shared__ __align__(16) float sm[];
    float* Wsm  = sm;                    // [12][512][4] = 24576 floats (96KB)
    float* h_s  = sm + 12 * 512 * 4;     // [128]
    float* acts = h_s + 128;             // [512]

    const int tid = threadIdx.x;
    const int b   = blockIdx.x;

    // Register weights: chunks 0..RC-1 of own row
    u64 wa[RC], wb[RC];
#pragma unroll
    for (int m = 0; m < RC; m++) {
        float4 w = *(const float4*)&Wh[(size_t)tid * H_ + m * 4];
        wa[m] = pk2(w.x, w.y);
        wb[m] = pk2(w.z, w.w);
    }
    // Smem weights: chunks RC..31 -> Wsm[jb][row][4]
    for (int idx = tid; idx < 12 * 512; idx += 512) {
        int jb = idx >> 9, r = idx & 511;
        *(float4*)&Wsm[(size_t)idx * 4] =
            *(const float4*)&Wh[(size_t)r * H_ + (RC + jb) * 4];
    }
    if (tid < H_) h_s[tid] = 0.0f;
    float cst = 0.0f;
    const bool is_tanh = ((tid >> 7) == 2);

    const float* gxb = GX + (size_t)b * T_ * G_;
    float* outb      = out + (size_t)b * T_ * H_;
    float gxv = 0.0f;
    __syncthreads();

    for (int t = 0; t < T_; t++) {
        if ((t & 127) == 0) {
            if (tid == 0) {
                const int fidx = (t >> 7) * 32 + b;
                unsigned v;
                do {
                    asm volatile("ld.global.acquire.gpu.u32 %0, [%1];"
                                 : "=r"(v) : "l"((const unsigned*)&g_flag[fidx]) : "memory");
                    if (v < 4u) __nanosleep(128);
                } while (v < 4u);
            }
            __syncthreads();
            gxv = ldcg(&gxb[(size_t)t * G_ + tid]);
        }

        const ulonglong2* h2 = (const ulonglong2*)h_s;   // chunk m -> h[4m..4m+3]
        u64 acc0 = pk2(0.0f, 0.0f), acc1 = pk2(0.0f, 0.0f);
#pragma unroll
        for (int m = 0; m < RC; m++) {
            ulonglong2 hh = h2[m];
            fma2(acc0, hh.x, wa[m]);
            fma2(acc1, hh.y, wb[m]);
        }
#pragma unroll
        for (int jb = 0; jb < 12; jb++) {
            ulonglong2 hh = h2[RC + jb];
            ulonglong2 ww = *(const ulonglong2*)&Wsm[(size_t)(jb * 512 + tid) * 4];
            fma2(acc0, hh.x, ww.x);
            fma2(acc1, hh.y, ww.y);
        }
        float2 u0 = upk2(acc0), u1 = upk2(acc1);
        float g = (u0.x + u0.y) + (u1.x + u1.y) + gxv;

        acts[tid] = is_tanh ? fast_tanh(g) : fast_sigmoid(g);
        if (((t + 1) & 127) != 0)
            gxv = ldcg(&gxb[(size_t)(t + 1) * G_ + tid]);
        __syncthreads();

        if (tid < H_) {
            float ig = acts[tid];
            float fg = acts[H_ + tid];
            float gg = acts[2 * H_ + tid];
            float og = acts[3 * H_ + tid];
            cst = fg * cst + ig * gg;
            float hv = og * fast_tanh(cst);
            h_s[tid] = hv;
            outb[(size_t)t * H_ + tid] = hv;
            if (t == T_ - 1) {
                hn[b * H_ + tid] = hv;
                cn[b * H_ + tid] = cst;
            }
        }
        __syncthreads();
    }
}

// ---------------------------------------------------------------------------
extern "C" void kernel_launch(void* const* d_in, const int* in_sizes, int n_in,
                              void* d_out, int out_size)
{
    const float* x   = (const float*)d_in[0];
    const float* Wih = (const float*)d_in[1];
    const float* Whh = (const float*)d_in[2];
    const float* bih = (const float*)d_in[3];
    const float* bhh = (const float*)d_in[4];
    float* out = (float*)d_out;

    float* gx = nullptr;
    cudaGetSymbolAddress((void**)&gx, g_gx);
    __nv_bfloat16* A2 = nullptr;
    cudaGetSymbolAddress((void**)&A2, g_A2);
    __nv_bfloat16* B2 = nullptr;
    cudaGetSymbolAddress((void**)&B2, g_B2);

    cudaFuncSetAttribute(gemm_mma_x, cudaFuncAttributeMaxDynamicSharedMemorySize,
                         GEMM_SMEM_PAD);
    cudaFuncSetAttribute(lstm_rec5, cudaFuncAttributeMaxDynamicSharedMemorySize,
                         REC_SMEM_PAD);

    cudaStream_t s2;
    cudaStreamCreateWithFlags(&s2, cudaStreamNonBlocking);
    cudaEvent_t e0, e1;
    cudaEventCreateWithFlags(&e0, cudaEventDisableTiming);
    cudaEventCreateWithFlags(&e1, cudaEventDisableTiming);

    // main: converts (full chip) + flag reset
    convert_split2<<<(B_ * T_ * (D_ / 4) + 255) / 256, 256>>>(x, A2, B_ * T_);
    convert_split2<<<(G_ * (D_ / 4) + 255) / 256, 256>>>(Wih, B2, G_);
    reset_flags<<<1, 256>>>();

    cudaEventRecord(e0, 0);
    cudaStreamWaitEvent(s2, e0, 0);

    // side stream: persistent GEMM (116 CTAs, 1/SM via smem pad)
    gemm_mma_x<<<GEMM_CTAS, 256, GEMM_SMEM_PAD, s2>>>(A2, B2, bih, bhh, gx);
    cudaEventRecord(e1, s2);

    // main: recurrence on 32 SMs (1 CTA/SM via smem pad), flag-gated
    lstm_rec5<<<B_, 512, REC_SMEM_PAD>>>(gx, Whh, out,
                                         out + (size_t)B_ * T_ * H_,
                                         out + (size_t)B_ * T_ * H_ + B_ * H_);

    // join side stream back into the main stream before capture ends
    cudaStreamWaitEvent(0, e1, 0);
}

// round 15
// speedup vs baseline: 1.6991x; 1.6991x over previous
#include <cuda_runtime.h>
#include <cuda_fp16.h>
#include <cstdint>

// LSTM: B=32, T=1024, D=1024, H=128  (gates 4H=512, order i,f,g,o)
// out layout: [B*T*H floats][h_n: B*H][c_n: B*H]

#define B_ 32
#define T_ 1024
#define D_ 1024
#define H_ 128
#define G_ 512
#define GEMM_CTAS 84      // 1 CTA/SM; rec4 clusters take the other 64 SMs
#define STAGE_BYTES 32768 // A 16KB + B 16KB per stage, 3 stages (128x128 tile)
#define GEMM_SMEM_PAD 122880  // 120KB: 1 GEMM CTA/SM; regs block rec colocation

typedef unsigned long long u64;

__device__ __forceinline__ u64 pk2(float x, float y) {
    u64 r;
    asm("mov.b64 %0, {%1, %2};" : "=l"(r)
        : "r"(__float_as_uint(x)), "r"(__float_as_uint(y)));
    return r;
}
__device__ __forceinline__ float2 upk2(u64 v) {
    unsigned lo, hi;
    asm("mov.b64 {%0, %1}, %2;" : "=r"(lo), "=r"(hi) : "l"(v));
    return make_float2(__uint_as_float(lo), __uint_as_float(hi));
}
__device__ __forceinline__ void fma2(u64 &c, u64 a, u64 b) {
    asm("fma.rn.f32x2 %0, %1, %2, %0;" : "+l"(c) : "l"(a), "l"(b));
}
__device__ __forceinline__ float fast_sigmoid(float x) {
    return 1.0f / (1.0f + __expf(-x));
}
__device__ __forceinline__ float fast_tanh(float x) {
    return 1.0f - 2.0f / (__expf(2.0f * x) + 1.0f);
}
__device__ __forceinline__ uint32_t smem_u32(const void* p) {
    uint32_t a;
    asm("{ .reg .u64 t; cvta.to.shared.u64 t, %1; cvt.u32.u64 %0, t; }"
        : "=r"(a) : "l"(p));
    return a;
}
// L2-coherent load: gx is written concurrently by the GEMM kernel.
__device__ __forceinline__ float ldcg(const float* p) {
    float v;
    asm volatile("ld.global.cg.f32 %0, [%1];" : "=f"(v) : "l"(p) : "memory");
    return v;
}
__device__ __forceinline__ void cp16(uint32_t dst, const void* src) {
    asm volatile("cp.async.cg.shared.global [%0], [%1], 16;"
                 :: "r"(dst), "l"(src));
}
__device__ __forceinline__ void ldsm4(uint32_t* r, uint32_t addr) {
    asm volatile("ldmatrix.sync.aligned.m8n8.x4.shared.b16 {%0,%1,%2,%3}, [%4];"
                 : "=r"(r[0]), "=r"(r[1]), "=r"(r[2]), "=r"(r[3]) : "r"(addr));
}
__device__ __forceinline__ void mma16816h(float* d, const uint32_t* a,
                                          uint32_t b0, uint32_t b1) {
    asm volatile(
        "mma.sync.aligned.m16n8k16.row.col.f32.f16.f16.f32 "
        "{%0,%1,%2,%3}, {%4,%5,%6,%7}, {%8,%9}, {%0,%1,%2,%3};"
        : "+f"(d[0]), "+f"(d[1]), "+f"(d[2]), "+f"(d[3])
        : "r"(a[0]), "r"(a[1]), "r"(a[2]), "r"(a[3]), "r"(b0), "r"(b1));
}

// Scratch (__device__ globals: allocation-free)
__device__ float g_gx[(size_t)B_ * T_ * G_];                 // 64 MB
__device__ __half g_A2[(size_t)B_ * T_ * 2048];              // 128 MB  [hi|mid]
__device__ __half g_B2[(size_t)G_ * 2048];                   // 2 MB    [hi|mid]
__device__ int g_flag[256];   // per m-tile completion counters (target 4)

__global__ void reset_flags() { g_flag[threadIdx.x] = 0; }

// ---------------------------------------------------------------------------
// fp32 -> 2-way fp16 split: hi = rn(x) [11 bits], mid = rn(x - hi) [11 more].
// Row layout: [hi(1024) | mid(1024)] half, row stride 2048.
// ---------------------------------------------------------------------------
__global__ void convert_split2h(const float* __restrict__ X,
                                __half* __restrict__ OUT, int rows)
{
    size_t i = (size_t)blockIdx.x * blockDim.x + threadIdx.x;
    size_t total = (size_t)rows * (D_ / 4);
    if (i >= total) return;
    float4 v = ((const float4*)X)[i];
    size_t m  = i >> 8;
    int   k4  = (int)(i & 255);

    float xs[4] = {v.x, v.y, v.z, v.w};
    __half hi[4], md[4];
#pragma unroll
    for (int c = 0; c < 4; c++) {
        hi[c] = __float2half_rn(xs[c]);
        float r1 = xs[c] - __half2float(hi[c]);   // exact
        md[c] = __float2half_rn(r1);
    }

    __half2* dh = (__half2*)(OUT + m * 2048 + k4 * 4);
    __half2* dm = (__half2*)(OUT + m * 2048 + 1024 + k4 * 4);
    dh[0] = __halves2half2(hi[0], hi[1]);
    dh[1] = __halves2half2(hi[2], hi[3]);
    dm[0] = __halves2half2(md[0], md[1]);
    dm[1] = __halves2half2(md[2], md[3]);
}

// ---------------------------------------------------------------------------
// PERSISTENT fp16 mma.sync GEMM, 2 phases: (Ah,Bh) + (Am,Bh) = A·Bh.
// Dropped Ah·Bm ~ 2^-12 of W -> final rel_err ~2-4e-4, under 1e-3.
// 128x128 tiles, 84 CTAs (1/SM via 120KB pad), 3-stage cp.async,
// tc-major tile order; each m-tile's 4 n-CTAs bump g_flag[y].
// ---------------------------------------------------------------------------
__global__ __launch_bounds__(256, 1) void gemm_mma_x(
    const __half* __restrict__ A2, const __half* __restrict__ B2,
    const float* __restrict__ b1, const float* __restrict__ b2,
    float* __restrict__ GX)
{
    extern __shared__ char smraw[];
    const uint32_t sbase = smem_u32(smraw);

    const int tid = threadIdx.x;
    const int wid = tid >> 5, lid = tid & 31;
    const int wm  = wid >> 2, wn = wid & 3;     // 2 x 4 warps, 64x32 each
    const int mat = lid >> 3, rin = lid & 7;
    const uint32_t aOff = (uint32_t)((((wm * 8 + (mat & 1)) * 8) + (mat >> 1)) * 128 + rin * 16);
    const uint32_t bOff = 16384u +
        (uint32_t)((((wn * 4 + (mat & 1)) * 8) + (mat >> 1)) * 128 + rin * 16);

    for (int tile = blockIdx.x; tile < 1024; tile += gridDim.x) {
        const int y  = tile >> 2;            // m-tile index, tc-major
        const int n0 = (tile & 3) * 128;
        const int bb = y & 31, tc = y >> 5;
        const int m0 = bb * 1024 + tc * 128;

        const char* Ab = (const char*)A2 + (size_t)m0 * 4096;
        const char* Bb = (const char*)B2 + (size_t)n0 * 4096;

        float acc[4][4][4];
#pragma unroll
        for (int i = 0; i < 4; i++)
#pragma unroll
            for (int j = 0; j < 4; j++)
#pragma unroll
                for (int r = 0; r < 4; r++) acc[i][j][r] = 0.0f;

// Phase p = kt>>4: 0 = (Ah,Bh), 1 = (Am,Bh). kk = kt & 15.
#define ISSUE(kt, st)                                                          \
    do {                                                                       \
        const int ph_ = (kt) >> 4, kk_ = (kt) & 15;                            \
        const int aoff_ = ((ph_ == 1) ? 2048 : 0) + kk_ * 128;                 \
        const int boff_ = kk_ * 128;                                           \
        uint32_t dA = sbase + (st) * STAGE_BYTES;                              \
        uint32_t dB = dA + 16384;                                              \
        _Pragma("unroll")                                                      \
        for (int it = 0; it < 4; it++) {                                       \
            int id = tid + it * 256;                                           \
            int mm = id >> 3, kg = id & 7;                                     \
            uint32_t doff = (uint32_t)((((mm >> 3) * 8) + kg) * 128 + (mm & 7) * 16); \
            cp16(dA + doff, Ab + (size_t)mm * 4096 + aoff_ + kg * 16);         \
            cp16(dB + doff, Bb + (size_t)mm * 4096 + boff_ + kg * 16);         \
        }                                                                      \
        asm volatile("cp.async.commit_group;" ::: "memory");                   \
    } while (0)

        ISSUE(0, 0);
        ISSUE(1, 1);

        const int NKT = 32;   // 2 phases x 16 k-tiles
        for (int kt = 0; kt < NKT; kt++) {
            const int st = kt % 3;
            if (kt + 1 < NKT) {
                asm volatile("cp.async.wait_group 1;" ::: "memory");
            } else {
                asm volatile("cp.async.wait_group 0;" ::: "memory");
            }
            __syncthreads();
            if (kt + 2 < NKT) ISSUE(kt + 2, (kt + 2) % 3);

            const uint32_t aS = sbase + st * STAGE_BYTES + aOff;
            const uint32_t bS = sbase + st * STAGE_BYTES + bOff;
#pragma unroll
            for (int ks = 0; ks < 4; ks++) {
                uint32_t af[4][4], bf[2][4];
#pragma unroll
                for (int i = 0; i < 4; i++)
                    ldsm4(af[i], aS + i * 2048 + ks * 256);
#pragma unroll
                for (int jp = 0; jp < 2; jp++)
                    ldsm4(bf[jp], bS + jp * 2048 + ks * 256);
#pragma unroll
                for (int i = 0; i < 4; i++)
#pragma unroll
                    for (int j = 0; j < 4; j++)
                        mma16816h(acc[i][j], af[i],
                                  bf[j >> 1][j & 1], bf[j >> 1][2 + (j & 1)]);
            }
        }

        // Epilogue: bias + store fp32, then signal tile completion
        const int mrow = lid >> 2;
        const int ncol = 2 * (lid & 3);
        float2 bj[4];
#pragma unroll
        for (int j = 0; j < 4; j++) {
            int n = n0 + wn * 32 + j * 8 + ncol;
            bj[j].x = b1[n] + b2[n];
            bj[j].y = b1[n + 1] + b2[n + 1];
        }
#pragma unroll
        for (int i = 0; i < 4; i++) {
            int r0 = m0 + wm * 64 + i * 16 + mrow;
#pragma unroll
            for (int j = 0; j < 4; j++) {
                int n = n0 + wn * 32 + j * 8 + ncol;
                float2 v0 = make_float2(acc[i][j][0] + bj[j].x, acc[i][j][1] + bj[j].y);
                float2 v1 = make_float2(acc[i][j][2] + bj[j].x, acc[i][j][3] + bj[j].y);
                *(float2*)&GX[(size_t)r0 * G_ + n]        = v0;
                *(float2*)&GX[(size_t)(r0 + 8) * G_ + n]  = v1;
            }
        }
        __threadfence();
        __syncthreads();
        if (tid == 0) atomicAdd(&g_flag[y], 1);
    }
}

// ---------------------------------------------------------------------------
// Recurrence v4 (proven 860us config): 2-CTA cluster per batch, register
// weights (64 floats/thread -> 122 regs, NO spills), st.async h exchange,
// per-128-step tile gating on g_flag (target 4), gx via ld.global.cg.
// ---------------------------------------------------------------------------
__global__ __launch_bounds__(512, 1) __cluster_dims__(2, 1, 1)
void lstm_rec4(const float* __restrict__ GX, const float* __restrict__ Wh,
               float* __restrict__ out, float* __restrict__ hn,
               float* __restrict__ cn)
{
    __shared__ __align__(16) float hbuf[2][128];
    __shared__ __align__(16) float acts[256];
    __shared__ __align__(8) unsigned long long mbar[2];

    const int tid = threadIdx.x;
    uint32_t rank;
    asm("mov.u32 %0, %%cluster_ctarank;" : "=r"(rank));
    const int b    = blockIdx.x >> 1;
    const int rl   = tid >> 1;
    const int p    = tid & 1;
    const int q    = rl >> 6;
    const int j    = rl & 63;
    const int grow = q * 128 + (int)rank * 64 + j;
    const int base = (int)rank * 8;

    u64 wa[16], wb[16];
#pragma unroll
    for (int m = 0; m < 16; m++) {
        int c = p + 2 * ((base + m) & 15);
        float4 w = *(const float4*)&Wh[(size_t)grow * H_ + c * 4];
        wa[m] = pk2(w.x, w.y);
        wb[m] = pk2(w.z, w.w);
    }

    if (tid < 128) { hbuf[0][tid] = 0.0f; hbuf[1][tid] = 0.0f; }
    uint32_t mb_loc0 = smem_u32(&mbar[0]);
    uint32_t mb_loc1 = smem_u32(&mbar[1]);
    if (tid == 0) {
        asm volatile("mbarrier.init.shared.b64 [%0], 1;" :: "r"(mb_loc0) : "memory");
        asm volatile("mbarrier.init.shared.b64 [%0], 1;" :: "r"(mb_loc1) : "memory");
        asm volatile("mbarrier.arrive.expect_tx.shared.b64 _, [%0], 256;" :: "r"(mb_loc0) : "memory");
        asm volatile("mbarrier.arrive.expect_tx.shared.b64 _, [%0], 256;" :: "r"(mb_loc1) : "memory");
    }

    uint32_t ph_peer0, ph_peer1, pm_peer0, pm_peer1;
    {
        const uint32_t r_ = rank ^ 1u;
        int hid = (int)rank * 64 + (tid & 63);
        uint32_t l0 = smem_u32(&hbuf[0][hid]);
        uint32_t l1 = smem_u32(&hbuf[1][hid]);
        asm("mapa.shared::cluster.u32 %0, %1, %2;" : "=r"(ph_peer0) : "r"(l0), "r"(r_));
        asm("mapa.shared::cluster.u32 %0, %1, %2;" : "=r"(ph_peer1) : "r"(l1), "r"(r_));
        asm("mapa.shared::cluster.u32 %0, %1, %2;" : "=r"(pm_peer0) : "r"(mb_loc0), "r"(r_));
        asm("mapa.shared::cluster.u32 %0, %1, %2;" : "=r"(pm_peer1) : "r"(mb_loc1), "r"(r_));
    }

    const float* gxb = GX + (size_t)b * T_ * G_;
    float* outb      = out + (size_t)b * T_ * H_;
    float gxv = 0.0f;
    float cst = 0.0f;
    int ph0 = 0, ph1 = 0;

    asm volatile("barrier.cluster.arrive.aligned;" ::: "memory");
    asm volatile("barrier.cluster.wait.aligned;" ::: "memory");

    for (int t = 0; t < T_; t++) {
        if ((t & 127) == 0) {
            if (tid == 0) {
                const int fidx = (t >> 7) * 32 + b;
                unsigned v;
                do {
                    asm volatile("ld.global.acquire.gpu.u32 %0, [%1];"
                                 : "=r"(v) : "l"((const unsigned*)&g_flag[fidx]) : "memory");
                    if (v < 4u) __nanosleep(128);
                } while (v < 4u);
            }
            __syncthreads();
            if (p == 0) gxv = ldcg(&gxb[(size_t)t * G_ + grow]);
        }

        const int cb = t & 1, nb = cb ^ 1;
        const ulonglong2* h2 = (const ulonglong2*)hbuf[cb];

        u64 acc0 = pk2(0.0f, 0.0f), acc1 = pk2(0.0f, 0.0f);
#pragma unroll
        for (int m = 0; m < 8; m++) {
            ulonglong2 hh = h2[p + 2 * ((base + m) & 15)];
            fma2(acc0, hh.x, wa[m]);
            fma2(acc1, hh.y, wb[m]);
        }
        if (t > 0) {
            uint32_t mb = cb ? mb_loc1 : mb_loc0;
            int par = cb ? ph1 : ph0;
            asm volatile(
                "{\n\t.reg .pred P;\n\t"
                "WL%=:\n\t"
                "mbarrier.try_wait.parity.acquire.cluster.shared::cta.b64 P, [%0], %1, 0x989680;\n\t"
                "@P bra WD%=;\n\t"
                "bra WL%=;\n\t"
                "WD%=:\n\t}"
                :: "r"(mb), "r"(par) : "memory");
            if (cb) ph1 ^= 1; else ph0 ^= 1;
            if (tid == 0)
                asm volatile("mbarrier.arrive.expect_tx.shared.b64 _, [%0], 256;"
                             :: "r"(mb) : "memory");
        }
#pragma unroll
        for (int m = 8; m < 16; m++) {
            ulonglong2 hh = h2[p + 2 * ((base + m) & 15)];
            fma2(acc0, hh.x, wa[m]);
            fma2(acc1, hh.y, wb[m]);
        }
        float2 u0 = upk2(acc0), u1 = upk2(acc1);
        float s = (u0.x + u0.y) + (u1.x + u1.y);
        s += __shfl_xor_sync(0xffffffffu, s, 1);

        if (p == 0) {
            float g = s + gxv;
            acts[rl] = (q == 2) ? fast_tanh(g) : fast_sigmoid(g);
            if (((t + 1) & 127) != 0)
                gxv = ldcg(&gxb[(size_t)(t + 1) * G_ + grow]);
        }
        __syncthreads();

        if (tid < 64) {
            float ig = acts[tid];
            float fg = acts[64 + tid];
            float gg = acts[128 + tid];
            float og = acts[192 + tid];
            cst = fg * cst + ig * gg;
            float hv = og * fast_tanh(cst);
            const int hid = (int)rank * 64 + tid;
            hbuf[nb][hid] = hv;
            {
                uint32_t pa = nb ? ph_peer1 : ph_peer0;
                uint32_t pm = nb ? pm_peer1 : pm_peer0;
                asm volatile(
                    "st.async.shared::cluster.mbarrier::complete_tx::bytes.b32 [%0], %1, [%2];"
                    :: "r"(pa), "r"(__float_as_uint(hv)), "r"(pm) : "memory");
            }
            outb[(size_t)t * H_ + hid] = hv;
            if (t == T_ - 1) {
                hn[b * H_ + hid] = hv;
                cn[b * H_ + hid] = cst;
            }
        }
        __syncthreads();
    }
}

// ---------------------------------------------------------------------------
extern "C" void kernel_launch(void* const* d_in, const int* in_sizes, int n_in,
                              void* d_out, int out_size)
{
    const float* x   = (const float*)d_in[0];
    const float* Wih = (const float*)d_in[1];
    const float* Whh = (const float*)d_in[2];
    const float* bih = (const float*)d_in[3];
    const float* bhh = (const float*)d_in[4];
    float* out = (float*)d_out;

    float* gx = nullptr;
    cudaGetSymbolAddress((void**)&gx, g_gx);
    __half* A2 = nullptr;
    cudaGetSymbolAddress((void**)&A2, g_A2);
    __half* B2 = nullptr;
    cudaGetSymbolAddress((void**)&B2, g_B2);

    cudaFuncSetAttribute(gemm_mma_x, cudaFuncAttributeMaxDynamicSharedMemorySize,
                         GEMM_SMEM_PAD);

    cudaStream_t s2;
    cudaStreamCreateWithFlags(&s2, cudaStreamNonBlocking);
    cudaEvent_t e0, e1;
    cudaEventCreateWithFlags(&e0, cudaEventDisableTiming);
    cudaEventCreateWithFlags(&e1, cudaEventDisableTiming);

    // main: converts (full chip) + flag reset
    convert_split2h<<<(B_ * T_ * (D_ / 4) + 255) / 256, 256>>>(x, A2, B_ * T_);
    convert_split2h<<<(G_ * (D_ / 4) + 255) / 256, 256>>>(Wih, B2, G_);
    reset_flags<<<1, 256>>>();

    cudaEventRecord(e0, 0);
    cudaStreamWaitEvent(s2, e0, 0);

    // side stream: persistent fp16 GEMM (84 CTAs, 1/SM via smem pad)
    gemm_mma_x<<<GEMM_CTAS, 256, GEMM_SMEM_PAD, s2>>>(A2, B2, bih, bhh, gx);
    cudaEventRecord(e1, s2);

    // main: recurrence clusters on the remaining 64 SMs, flag-gated
    float* hn = out + (size_t)B_ * T_ * H_;
    float* cn = hn + (size_t)B_ * H_;
    lstm_rec4<<<B_ * 2, 512>>>(gx, Whh, out, hn, cn);

    // join side stream back into the main stream before capture ends
    cudaStreamWaitEvent(0, e1, 0);
}